// round 1
// baseline (speedup 1.0000x reference)
#include <cuda_runtime.h>
#include <cuda_bf16.h>
#include <math.h>

// ---------------- problem constants ----------------
#define Bb    64
#define Cc    2048
#define LL    196
#define L1    197           // pooled + features
#define HID   2048
#define OUTC  256
#define NH    8
#define CH    (Cc / NH)     // 256 channels per head
#define KH    (OUTC / NH)   // 32 attn slots per head
#define N1    (Bb * L1)     // 12608 rows of MLP-p
#define N2    (Bb * KH)     // 2048 rows of MLP-o

// output packing offsets (z_g, obj_val, obj_attn, obj_attn_raw)
#define OFF_ZG    0
#define OFF_VAL   (Bb * OUTC)                         // 16384
#define OFF_ATTN  (OFF_VAL + Bb * OUTC * KH)          // 540672
#define OFF_RAW   (OFF_ATTN + Bb * NH * KH * LL)      // 3751936

// ---------------- device scratch (no runtime allocation allowed) ----------------
__device__ float d_X1[(size_t)N1 * Cc];      // (b, l, c)  103 MB
__device__ float d_H1[(size_t)N1 * HID];     // 103 MB
__device__ float d_Z [(size_t)N1 * OUTC];    // 12.9 MB
__device__ float d_Vt[(size_t)N2 * Cc];      // 16.8 MB
__device__ float d_H2[(size_t)N2 * HID];     // 16.8 MB
__device__ float d_C4[(size_t)N2 * OUTC];    // 2 MB
__device__ float d_nrm[Bb * LL];
__device__ float d_part_s[64 * HID];
__device__ float d_part_q[64 * HID];
__device__ float d_scale[HID];
__device__ float d_shift[HID];

// ---------------- stage 0: pool (mean over L) -> X1 row l=0 ----------------
__global__ void pool_kernel(const float* __restrict__ x) {
    int wid  = (blockIdx.x * blockDim.x + threadIdx.x) >> 5;
    int lane = threadIdx.x & 31;
    if (wid >= Bb * Cc) return;
    int b = wid >> 11, c = wid & (Cc - 1);
    const float* xr = x + ((size_t)b * Cc + c) * LL;
    float s = 0.f;
    for (int l = lane; l < LL; l += 32) s += xr[l];
    #pragma unroll
    for (int o = 16; o; o >>= 1) s += __shfl_down_sync(~0u, s, o);
    if (lane == 0) d_X1[((size_t)b * L1) * Cc + c] = s * (1.f / (float)LL);
}

// ---------------- stage 0b: transpose x (b,c,l) -> X1 (b, 1+l, c) ----------------
__global__ void transpose_kernel(const float* __restrict__ x) {
    __shared__ float t[32][33];
    int b  = blockIdx.z;
    int c0 = blockIdx.y * 32;
    int l0 = blockIdx.x * 32;
    int tx = threadIdx.x, ty = threadIdx.y;
    #pragma unroll
    for (int i = 0; i < 32; i += 8) {
        int c = c0 + ty + i, l = l0 + tx;
        t[ty + i][tx] = (l < LL) ? x[((size_t)b * Cc + c) * LL + l] : 0.f;
    }
    __syncthreads();
    #pragma unroll
    for (int i = 0; i < 32; i += 8) {
        int l = l0 + ty + i, c = c0 + tx;
        if (l < LL)
            d_X1[((size_t)b * L1 + 1 + l) * Cc + c] = t[tx][ty + i];
    }
}

// ---------------- generic TN SGEMM: C[N,M] = op(A)[N,K] * W[M,K]^T ----------------
// FUSE: A element (row, k) -> relu(a * scale[k] + shift[k])
template <int BM, int BN, int BK, int TM, int TN, bool FUSE>
__global__ __launch_bounds__(256)
void gemm_tn(const float* __restrict__ A, const float* __restrict__ W,
             float* __restrict__ C, int N, int M, int K,
             const float* __restrict__ scale, const float* __restrict__ shift)
{
    __shared__ float As[BK][BM];
    __shared__ float Bs[BK][BN];
    const int tid  = threadIdx.x;
    const int row0 = blockIdx.y * BM;
    const int col0 = blockIdx.x * BN;
    constexpr int KQ = BK / 4;            // float4 slots per row
    const int lr = tid / KQ;
    const int lk = (tid % KQ) * 4;
    const int tx = tid % (BN / TN);
    const int ty = tid / (BN / TN);
    float acc[TM][TN] = {};

    for (int k0 = 0; k0 < K; k0 += BK) {
        float4 av = make_float4(0.f, 0.f, 0.f, 0.f);
        int ar = row0 + lr;
        if (ar < N) {
            av = *reinterpret_cast<const float4*>(A + (size_t)ar * K + k0 + lk);
            if (FUSE) {
                av.x = fmaxf(fmaf(av.x, scale[k0 + lk + 0], shift[k0 + lk + 0]), 0.f);
                av.y = fmaxf(fmaf(av.y, scale[k0 + lk + 1], shift[k0 + lk + 1]), 0.f);
                av.z = fmaxf(fmaf(av.z, scale[k0 + lk + 2], shift[k0 + lk + 2]), 0.f);
                av.w = fmaxf(fmaf(av.w, scale[k0 + lk + 3], shift[k0 + lk + 3]), 0.f);
            }
        }
        As[lk + 0][lr] = av.x; As[lk + 1][lr] = av.y;
        As[lk + 2][lr] = av.z; As[lk + 3][lr] = av.w;

        float4 wv = make_float4(0.f, 0.f, 0.f, 0.f);
        int wr = col0 + lr;
        if (wr < M)
            wv = *reinterpret_cast<const float4*>(W + (size_t)wr * K + k0 + lk);
        Bs[lk + 0][lr] = wv.x; Bs[lk + 1][lr] = wv.y;
        Bs[lk + 2][lr] = wv.z; Bs[lk + 3][lr] = wv.w;
        __syncthreads();

        #pragma unroll
        for (int kk = 0; kk < BK; kk++) {
            float a[TM], bv[TN];
            #pragma unroll
            for (int i = 0; i < TM; i++) a[i]  = As[kk][ty * TM + i];
            #pragma unroll
            for (int j = 0; j < TN; j++) bv[j] = Bs[kk][tx * TN + j];
            #pragma unroll
            for (int i = 0; i < TM; i++)
                #pragma unroll
                for (int j = 0; j < TN; j++)
                    acc[i][j] = fmaf(a[i], bv[j], acc[i][j]);
        }
        __syncthreads();
    }

    #pragma unroll
    for (int i = 0; i < TM; i++) {
        int r = row0 + ty * TM + i;
        if (r >= N) continue;
        #pragma unroll
        for (int j = 0; j < TN; j++) {
            int c = col0 + tx * TN + j;
            if (c < M) C[(size_t)r * M + c] = acc[i][j];
        }
    }
}

// ---------------- BN stats (deterministic two-stage) ----------------
__global__ void bn_partial(const float* __restrict__ Hm, int N, int rpc) {
    int o = blockIdx.x * 32 + threadIdx.x;
    int chunk = blockIdx.y;
    int r0 = chunk * rpc;
    int r1 = min(r0 + rpc, N);
    float s = 0.f, q = 0.f;
    for (int r = r0 + threadIdx.y; r < r1; r += 8) {
        float v = Hm[(size_t)r * HID + o];
        s += v; q += v * v;
    }
    __shared__ float ss[8][32], qq[8][32];
    ss[threadIdx.y][threadIdx.x] = s;
    qq[threadIdx.y][threadIdx.x] = q;
    __syncthreads();
    if (threadIdx.y == 0) {
        #pragma unroll
        for (int i = 1; i < 8; i++) { s += ss[i][threadIdx.x]; q += qq[i][threadIdx.x]; }
        d_part_s[chunk * HID + o] = s;
        d_part_q[chunk * HID + o] = q;
    }
}

__global__ void bn_final(const float* __restrict__ g, const float* __restrict__ bta,
                         float invN) {
    int o = blockIdx.x * 256 + threadIdx.x;
    float s = 0.f, q = 0.f;
    for (int ch = 0; ch < 64; ch++) { s += d_part_s[ch * HID + o]; q += d_part_q[ch * HID + o]; }
    float mu  = s * invN;
    float var = q * invN - mu * mu;
    float sc  = g[o] * rsqrtf(var + 1e-5f);
    d_scale[o] = sc;
    d_shift[o] = bta[o] - mu * sc;
}

// ---------------- z_g extraction ----------------
__global__ void zg_kernel(float* __restrict__ out) {
    int idx = blockIdx.x * 256 + threadIdx.x;     // 16384
    int b = idx >> 8, j = idx & 255;
    out[OFF_ZG + idx] = d_Z[((size_t)b * L1) * OUTC + j];
}

// ---------------- feature L2 norm over channels ----------------
__global__ void norm_kernel() {
    int bl = blockIdx.x;                          // 0 .. Bb*LL-1
    int b = bl / LL, l = bl % LL;
    float v = d_Z[((size_t)b * L1 + 1 + l) * OUTC + threadIdx.x];
    float s = v * v;
    #pragma unroll
    for (int o = 16; o; o >>= 1) s += __shfl_down_sync(~0u, s, o);
    __shared__ float w[8];
    if ((threadIdx.x & 31) == 0) w[threadIdx.x >> 5] = s;
    __syncthreads();
    if (threadIdx.x == 0) {
        float t = 0.f;
        #pragma unroll
        for (int i = 0; i < 8; i++) t += w[i];
        d_nrm[bl] = sqrtf(t);
    }
}

// ---------------- softmax over L per (b, channel j) ----------------
__global__ void softmax_kernel(float* __restrict__ out) {
    int wg   = (blockIdx.x * blockDim.x + threadIdx.x) >> 5;   // 0..16383
    int lane = threadIdx.x & 31;
    if (wg >= Bb * OUTC) return;
    int b = wg >> 8, j = wg & 255;
    float v[7];
    float mx = -INFINITY;
    #pragma unroll
    for (int i = 0; i < 7; i++) {
        int l = lane + i * 32;
        if (l < LL) {
            float n = d_nrm[b * LL + l];
            v[i] = d_Z[((size_t)b * L1 + 1 + l) * OUTC + j] / fmaxf(n, 1e-12f);
            mx = fmaxf(mx, v[i]);
        } else v[i] = -INFINITY;
    }
    #pragma unroll
    for (int o = 16; o; o >>= 1) mx = fmaxf(mx, __shfl_xor_sync(~0u, mx, o));
    float s = 0.f;
    #pragma unroll
    for (int i = 0; i < 7; i++) { v[i] = expf(v[i] - mx); s += v[i]; }
    #pragma unroll
    for (int o = 16; o; o >>= 1) s += __shfl_xor_sync(~0u, s, o);
    float inv = 1.f / s;
    #pragma unroll
    for (int i = 0; i < 7; i++) {
        int l = lane + i * 32;
        if (l < LL) {
            float r = v[i] * inv;
            size_t idx = ((size_t)b * OUTC + j) * LL + l;
            out[OFF_ATTN + idx] = r;
            out[OFF_RAW  + idx] = r;
        }
    }
}

// ---------------- attention-value einsum: Vt[(b,k), h*256+c'] ----------------
__global__ __launch_bounds__(256)
void attnval_kernel(const float* __restrict__ x, const float* __restrict__ out) {
    const float* attn = out + OFF_ATTN;
    int h = blockIdx.x, b = blockIdx.y;
    __shared__ float xs[256][33];     // [c'][l-chunk]
    __shared__ float as2[32][36];     // [l-chunk][k] padded for float4
    int tid = threadIdx.x;
    float acc[KH] = {};

    for (int l0 = 0; l0 < LL; l0 += 32) {
        int lmax = min(32, LL - l0);
        // load x chunk coalesced: 256 c' x 32 l
        #pragma unroll
        for (int i = 0; i < 32; i++) {
            int row = (tid >> 5) + i * 8;
            int col = tid & 31;
            float v = 0.f;
            if (l0 + col < LL)
                v = x[((size_t)b * Cc + h * CH + row) * LL + l0 + col];
            xs[row][col] = v;
        }
        // load attn chunk transposed: as2[l][k]
        #pragma unroll
        for (int i = 0; i < 4; i++) {
            int k   = (tid >> 5) + i * 8;
            int col = tid & 31;
            float v = 0.f;
            if (l0 + col < LL)
                v = attn[(((size_t)b * NH + h) * KH + k) * LL + l0 + col];
            as2[col][k] = v;
        }
        __syncthreads();
        for (int l = 0; l < lmax; l++) {
            float xv = xs[tid][l];
            #pragma unroll
            for (int k4 = 0; k4 < KH / 4; k4++) {
                float4 w = *reinterpret_cast<const float4*>(&as2[l][k4 * 4]);
                acc[k4 * 4 + 0] = fmaf(xv, w.x, acc[k4 * 4 + 0]);
                acc[k4 * 4 + 1] = fmaf(xv, w.y, acc[k4 * 4 + 1]);
                acc[k4 * 4 + 2] = fmaf(xv, w.z, acc[k4 * 4 + 2]);
                acc[k4 * 4 + 3] = fmaf(xv, w.w, acc[k4 * 4 + 3]);
            }
        }
        __syncthreads();
    }
    #pragma unroll
    for (int k = 0; k < KH; k++)
        d_Vt[((size_t)b * KH + k) * Cc + h * CH + tid] = acc[k];
}

// ---------------- final permute: C4[(b,k), j] -> out[(b, j, k)] ----------------
__global__ void permute_kernel(float* __restrict__ out) {
    int idx = blockIdx.x * 256 + threadIdx.x;        // 524288
    int b = idx >> 13;
    int rem = idx & 8191;
    int j = rem >> 5;
    int k = rem & 31;
    out[OFF_VAL + idx] = d_C4[((size_t)b * KH + k) * OUTC + j];
}

// ---------------- launch ----------------
extern "C" void kernel_launch(void* const* d_in, const int* in_sizes, int n_in,
                              void* d_out, int out_size) {
    const float* x    = (const float*)d_in[0];
    const float* w1_p = (const float*)d_in[1];
    const float* g_p  = (const float*)d_in[2];
    const float* b_p  = (const float*)d_in[3];
    const float* w2_p = (const float*)d_in[4];
    const float* w1_o = (const float*)d_in[5];
    const float* g_o  = (const float*)d_in[6];
    const float* b_o  = (const float*)d_in[7];
    const float* w2_o = (const float*)d_in[8];
    float* out = (float*)d_out;

    float *pX1, *pH1, *pZ, *pVt, *pH2, *pC4, *pScale, *pShift;
    cudaGetSymbolAddress((void**)&pX1,    d_X1);
    cudaGetSymbolAddress((void**)&pH1,    d_H1);
    cudaGetSymbolAddress((void**)&pZ,     d_Z);
    cudaGetSymbolAddress((void**)&pVt,    d_Vt);
    cudaGetSymbolAddress((void**)&pH2,    d_H2);
    cudaGetSymbolAddress((void**)&pC4,    d_C4);
    cudaGetSymbolAddress((void**)&pScale, d_scale);
    cudaGetSymbolAddress((void**)&pShift, d_shift);

    // 0) build X1 = concat(pool, x) transposed to (b, l, c)
    pool_kernel<<<(Bb * Cc) / 8, 256>>>(x);
    transpose_kernel<<<dim3((LL + 31) / 32, Cc / 32, Bb), dim3(32, 8)>>>(x);

    // 1) H1 = X1 @ w1_p^T   (12608 x 2048 x 2048)
    gemm_tn<128, 128, 8, 8, 8, false><<<dim3(HID / 128, (N1 + 127) / 128), 256>>>(
        pX1, w1_p, pH1, N1, HID, Cc, nullptr, nullptr);

    // 2) BN stats over rows, fold gamma/beta
    bn_partial<<<dim3(HID / 32, 64), dim3(32, 8)>>>(pH1, N1, (N1 + 63) / 64);
    bn_final<<<HID / 256, 256>>>(g_p, b_p, 1.f / (float)N1);

    // 3) Z = relu(bn(H1)) @ w2_p^T   (12608 x 256 x 2048), BN fused in A-load
    gemm_tn<64, 64, 16, 4, 4, true><<<dim3(OUTC / 64, (N1 + 63) / 64), 256>>>(
        pH1, w2_p, pZ, N1, OUTC, HID, pScale, pShift);

    // 4) outputs z_g; norms; softmax -> obj_attn / obj_attn_raw
    zg_kernel<<<(Bb * OUTC) / 256, 256>>>(out);
    norm_kernel<<<Bb * LL, 256>>>();
    softmax_kernel<<<(Bb * OUTC) / 8, 256>>>(out);

    // 5) Vt[(b,k), c] = sum_l x[b,c,l] * attn[b,h,k,l]
    attnval_kernel<<<dim3(NH, Bb), 256>>>(x, out);

    // 6) H2 = Vt @ w1_o^T   (2048 x 2048 x 2048)
    gemm_tn<128, 128, 8, 8, 8, false><<<dim3(HID / 128, N2 / 128), 256>>>(
        pVt, w1_o, pH2, N2, HID, Cc, nullptr, nullptr);

    // 7) BN stats 2
    bn_partial<<<dim3(HID / 32, 64), dim3(32, 8)>>>(pH2, N2, N2 / 64);
    bn_final<<<HID / 256, 256>>>(g_o, b_o, 1.f / (float)N2);

    // 8) C4 = relu(bn(H2)) @ w2_o^T  (2048 x 256 x 2048)
    gemm_tn<64, 64, 16, 4, 4, true><<<dim3(OUTC / 64, N2 / 64), 256>>>(
        pH2, w2_o, pC4, N2, OUTC, HID, pScale, pShift);

    // 9) permute to obj_val layout (b, 256, 32)
    permute_kernel<<<(Bb * OUTC * KH) / 256, 256>>>(out);
}

// round 2
// speedup vs baseline: 2.8767x; 2.8767x over previous
#include <cuda_runtime.h>
#include <cuda_bf16.h>
#include <math.h>
#include <stdint.h>

// ---------------- problem constants ----------------
#define Bb    64
#define Cc    2048
#define LL    196
#define L1    197           // pooled + features
#define HID   2048
#define OUTC  256
#define NH    8
#define CH    (Cc / NH)     // 256 channels per head
#define KH    (OUTC / NH)   // 32 attn slots per head
#define N1    (Bb * L1)     // 12608 rows of MLP-p
#define N2    (Bb * KH)     // 2048 rows of MLP-o

// output packing offsets (z_g, obj_val, obj_attn, obj_attn_raw)
#define OFF_ZG    0
#define OFF_VAL   (Bb * OUTC)                         // 16384
#define OFF_ATTN  (OFF_VAL + Bb * OUTC * KH)          // 540672
#define OFF_RAW   (OFF_ATTN + Bb * NH * KH * LL)      // 3751936

// ---------------- device scratch ----------------
__device__ float d_X1[(size_t)N1 * Cc];      // (b, l, c)  tf32-rounded
__device__ float d_H1[(size_t)N1 * HID];
__device__ float d_Z [(size_t)N1 * OUTC];
__device__ float d_Vt[(size_t)N2 * Cc];
__device__ float d_H2[(size_t)N2 * HID];
__device__ float d_C4[(size_t)N2 * OUTC];
__device__ float d_nrm[Bb * LL];
__device__ float d_part_s[64 * HID];
__device__ float d_part_q[64 * HID];
__device__ float d_scale[HID];
__device__ float d_shift[HID];
// tf32-rounded weight copies
__device__ float d_W1p[(size_t)HID * Cc];
__device__ float d_W2p[(size_t)OUTC * HID];
__device__ float d_W1o[(size_t)HID * Cc];
__device__ float d_W2o[(size_t)OUTC * HID];

// ---------------- helpers ----------------
__device__ __forceinline__ float tf32r(float x) {
    uint32_t u;
    asm("cvt.rna.tf32.f32 %0, %1;" : "=r"(u) : "f"(x));
    return __uint_as_float(u);
}

__device__ __forceinline__ void cpasync16(void* smem, const void* g, bool pred) {
    uint32_t s = (uint32_t)__cvta_generic_to_shared(smem);
    int sz = pred ? 16 : 0;
    asm volatile("cp.async.cg.shared.global [%0], [%1], 16, %2;"
                 :: "r"(s), "l"(g), "r"(sz));
}

// ---------------- stage 0: pool (mean over L) -> X1 row l=0 ----------------
__global__ void pool_kernel(const float* __restrict__ x) {
    int wid  = (blockIdx.x * blockDim.x + threadIdx.x) >> 5;
    int lane = threadIdx.x & 31;
    if (wid >= Bb * Cc) return;
    int b = wid >> 11, c = wid & (Cc - 1);
    const float* xr = x + ((size_t)b * Cc + c) * LL;
    float s = 0.f;
    for (int l = lane; l < LL; l += 32) s += xr[l];
    #pragma unroll
    for (int o = 16; o; o >>= 1) s += __shfl_down_sync(~0u, s, o);
    if (lane == 0) d_X1[((size_t)b * L1) * Cc + c] = tf32r(s * (1.f / (float)LL));
}

// ---------------- stage 0b: transpose x (b,c,l) -> X1 (b, 1+l, c), tf32-rounded --------
__global__ void transpose_kernel(const float* __restrict__ x) {
    __shared__ float t[32][33];
    int b  = blockIdx.z;
    int c0 = blockIdx.y * 32;
    int l0 = blockIdx.x * 32;
    int tx = threadIdx.x, ty = threadIdx.y;
    #pragma unroll
    for (int i = 0; i < 32; i += 8) {
        int c = c0 + ty + i, l = l0 + tx;
        t[ty + i][tx] = (l < LL) ? x[((size_t)b * Cc + c) * LL + l] : 0.f;
    }
    __syncthreads();
    #pragma unroll
    for (int i = 0; i < 32; i += 8) {
        int l = l0 + ty + i, c = c0 + tx;
        if (l < LL)
            d_X1[((size_t)b * L1 + 1 + l) * Cc + c] = tf32r(t[tx][ty + i]);
    }
}

// ---------------- tf32 round-copy for weights ----------------
__global__ void round_copy(const float* __restrict__ src, float* __restrict__ dst, int n4) {
    int i = blockIdx.x * 256 + threadIdx.x;
    if (i >= n4) return;
    float4 v = reinterpret_cast<const float4*>(src)[i];
    v.x = tf32r(v.x); v.y = tf32r(v.y); v.z = tf32r(v.z); v.w = tf32r(v.w);
    reinterpret_cast<float4*>(dst)[i] = v;
}

// ================= TF32 tensor-core GEMM =================
// C[N,M] = A[N,K] * W[M,K]^T ; A, W pre-rounded to tf32; C fp32.
// Warp tile 32x64 (2 m-tiles x 8 n-tiles of m16n8k8). Block = (32*WM) x (64*WN).
template <int WM, int WN>
__global__ __launch_bounds__(WM * WN * 32)
void gemm_tf32(const float* __restrict__ A, const float* __restrict__ W,
               float* __restrict__ C, int N, int M, int K)
{
    constexpr int BM = 32 * WM;
    constexpr int BN = 64 * WN;
    constexpr int BK = 16;
    constexpr int LDS = BK + 4;        // 20 floats stride (conflict-free fragments)
    constexpr int THREADS = WM * WN * 32;

    __shared__ float As[2][BM][LDS];
    __shared__ float Bs[2][BN][LDS];

    const int tid  = threadIdx.x;
    const int row0 = blockIdx.y * BM;
    const int col0 = blockIdx.x * BN;
    const int warp = tid >> 5, lane = tid & 31;
    const int g = lane >> 2, tg = lane & 3;
    const int wm = warp / WN, wn = warp % WN;
    const int m_base = wm * 32, n_base = wn * 64;

    float acc[2][8][4] = {};

    const int lr = tid >> 2;            // row within tile chunk
    const int lc = (tid & 3) * 4;       // float4 column (0,4,8,12)
    constexpr int RPI = THREADS / 4;    // rows loaded per pass
    constexpr int ITA = BM / RPI;
    constexpr int ITB = BN / RPI;

    auto loadTiles = [&](int k0, int st) {
        #pragma unroll
        for (int i = 0; i < ITA; i++) {
            int r = lr + i * RPI;
            bool p = (row0 + r) < N;
            const float* ga = A + (size_t)(p ? (row0 + r) : 0) * K + k0 + lc;
            cpasync16(&As[st][r][lc], ga, p);
        }
        #pragma unroll
        for (int i = 0; i < ITB; i++) {
            int r = lr + i * RPI;
            bool p = (col0 + r) < M;
            const float* gw = W + (size_t)(p ? (col0 + r) : 0) * K + k0 + lc;
            cpasync16(&Bs[st][r][lc], gw, p);
        }
        asm volatile("cp.async.commit_group;");
    };

    loadTiles(0, 0);
    const int nIter = K / BK;

    for (int it = 0; it < nIter; it++) {
        const int st = it & 1;
        if (it + 1 < nIter) {
            loadTiles((it + 1) * BK, st ^ 1);
            asm volatile("cp.async.wait_group 1;");
        } else {
            asm volatile("cp.async.wait_group 0;");
        }
        __syncthreads();

        #pragma unroll
        for (int kt = 0; kt < BK / 8; kt++) {
            const int k = kt * 8;
            uint32_t a[2][4], b[8][2];
            #pragma unroll
            for (int i = 0; i < 2; i++) {
                int m = m_base + i * 16;
                a[i][0] = __float_as_uint(As[st][m + g    ][k + tg    ]);
                a[i][1] = __float_as_uint(As[st][m + g + 8][k + tg    ]);
                a[i][2] = __float_as_uint(As[st][m + g    ][k + tg + 4]);
                a[i][3] = __float_as_uint(As[st][m + g + 8][k + tg + 4]);
            }
            #pragma unroll
            for (int j = 0; j < 8; j++) {
                int n = n_base + j * 8;
                b[j][0] = __float_as_uint(Bs[st][n + g][k + tg    ]);
                b[j][1] = __float_as_uint(Bs[st][n + g][k + tg + 4]);
            }
            #pragma unroll
            for (int i = 0; i < 2; i++)
                #pragma unroll
                for (int j = 0; j < 8; j++)
                    asm volatile(
                        "mma.sync.aligned.m16n8k8.row.col.f32.tf32.tf32.f32 "
                        "{%0,%1,%2,%3}, {%4,%5,%6,%7}, {%8,%9}, {%0,%1,%2,%3};"
                        : "+f"(acc[i][j][0]), "+f"(acc[i][j][1]),
                          "+f"(acc[i][j][2]), "+f"(acc[i][j][3])
                        : "r"(a[i][0]), "r"(a[i][1]), "r"(a[i][2]), "r"(a[i][3]),
                          "r"(b[j][0]), "r"(b[j][1]));
        }
        __syncthreads();
    }

    #pragma unroll
    for (int i = 0; i < 2; i++) {
        int mrow = row0 + m_base + i * 16;
        #pragma unroll
        for (int j = 0; j < 8; j++) {
            int c = col0 + n_base + j * 8 + tg * 2;
            int ra = mrow + g, rb = mrow + g + 8;
            if (ra < N) {
                float2 v = make_float2(acc[i][j][0], acc[i][j][1]);
                *reinterpret_cast<float2*>(&C[(size_t)ra * M + c]) = v;
            }
            if (rb < N) {
                float2 v = make_float2(acc[i][j][2], acc[i][j][3]);
                *reinterpret_cast<float2*>(&C[(size_t)rb * M + c]) = v;
            }
        }
    }
}

// ---------------- BN stats (deterministic two-stage) ----------------
__global__ void bn_partial(const float* __restrict__ Hm, int N, int rpc) {
    int o = blockIdx.x * 32 + threadIdx.x;
    int chunk = blockIdx.y;
    int r0 = chunk * rpc;
    int r1 = min(r0 + rpc, N);
    float s = 0.f, q = 0.f;
    for (int r = r0 + threadIdx.y; r < r1; r += 8) {
        float v = Hm[(size_t)r * HID + o];
        s += v; q += v * v;
    }
    __shared__ float ss[8][32], qq[8][32];
    ss[threadIdx.y][threadIdx.x] = s;
    qq[threadIdx.y][threadIdx.x] = q;
    __syncthreads();
    if (threadIdx.y == 0) {
        #pragma unroll
        for (int i = 1; i < 8; i++) { s += ss[i][threadIdx.x]; q += qq[i][threadIdx.x]; }
        d_part_s[chunk * HID + o] = s;
        d_part_q[chunk * HID + o] = q;
    }
}

__global__ void bn_final(const float* __restrict__ g, const float* __restrict__ bta,
                         float invN) {
    int o = blockIdx.x * 256 + threadIdx.x;
    float s = 0.f, q = 0.f;
    for (int ch = 0; ch < 64; ch++) { s += d_part_s[ch * HID + o]; q += d_part_q[ch * HID + o]; }
    float mu  = s * invN;
    float var = q * invN - mu * mu;
    float sc  = g[o] * rsqrtf(var + 1e-5f);
    d_scale[o] = sc;
    d_shift[o] = bta[o] - mu * sc;
}

// ---------------- BN + ReLU + tf32-round, in place ----------------
__global__ void bnrelu_kernel(float* __restrict__ Hm, int n4) {
    int i = blockIdx.x * 256 + threadIdx.x;
    if (i >= n4) return;
    int c = (i * 4) & (HID - 1);
    float4 v = reinterpret_cast<float4*>(Hm)[i];
    v.x = tf32r(fmaxf(fmaf(v.x, d_scale[c + 0], d_shift[c + 0]), 0.f));
    v.y = tf32r(fmaxf(fmaf(v.y, d_scale[c + 1], d_shift[c + 1]), 0.f));
    v.z = tf32r(fmaxf(fmaf(v.z, d_scale[c + 2], d_shift[c + 2]), 0.f));
    v.w = tf32r(fmaxf(fmaf(v.w, d_scale[c + 3], d_shift[c + 3]), 0.f));
    reinterpret_cast<float4*>(Hm)[i] = v;
}

// ---------------- z_g extraction ----------------
__global__ void zg_kernel(float* __restrict__ out) {
    int idx = blockIdx.x * 256 + threadIdx.x;     // 16384
    int b = idx >> 8, j = idx & 255;
    out[OFF_ZG + idx] = d_Z[((size_t)b * L1) * OUTC + j];
}

// ---------------- feature L2 norm over channels ----------------
__global__ void norm_kernel() {
    int bl = blockIdx.x;
    int b = bl / LL, l = bl % LL;
    float v = d_Z[((size_t)b * L1 + 1 + l) * OUTC + threadIdx.x];
    float s = v * v;
    #pragma unroll
    for (int o = 16; o; o >>= 1) s += __shfl_down_sync(~0u, s, o);
    __shared__ float w[8];
    if ((threadIdx.x & 31) == 0) w[threadIdx.x >> 5] = s;
    __syncthreads();
    if (threadIdx.x == 0) {
        float t = 0.f;
        #pragma unroll
        for (int i = 0; i < 8; i++) t += w[i];
        d_nrm[bl] = sqrtf(t);
    }
}

// ---------------- softmax over L per (b, channel j) ----------------
__global__ void softmax_kernel(float* __restrict__ out) {
    int wg   = (blockIdx.x * blockDim.x + threadIdx.x) >> 5;
    int lane = threadIdx.x & 31;
    if (wg >= Bb * OUTC) return;
    int b = wg >> 8, j = wg & 255;
    float v[7];
    float mx = -INFINITY;
    #pragma unroll
    for (int i = 0; i < 7; i++) {
        int l = lane + i * 32;
        if (l < LL) {
            float n = d_nrm[b * LL + l];
            v[i] = d_Z[((size_t)b * L1 + 1 + l) * OUTC + j] / fmaxf(n, 1e-12f);
            mx = fmaxf(mx, v[i]);
        } else v[i] = -INFINITY;
    }
    #pragma unroll
    for (int o = 16; o; o >>= 1) mx = fmaxf(mx, __shfl_xor_sync(~0u, mx, o));
    float s = 0.f;
    #pragma unroll
    for (int i = 0; i < 7; i++) { v[i] = expf(v[i] - mx); s += v[i]; }
    #pragma unroll
    for (int o = 16; o; o >>= 1) s += __shfl_xor_sync(~0u, s, o);
    float inv = 1.f / s;
    #pragma unroll
    for (int i = 0; i < 7; i++) {
        int l = lane + i * 32;
        if (l < LL) {
            float r = v[i] * inv;
            size_t idx = ((size_t)b * OUTC + j) * LL + l;
            out[OFF_ATTN + idx] = r;
            out[OFF_RAW  + idx] = r;
        }
    }
}

// ---------------- attention-value einsum ----------------
__global__ __launch_bounds__(256)
void attnval_kernel(const float* __restrict__ x, const float* __restrict__ out) {
    const float* attn = out + OFF_ATTN;
    int h = blockIdx.x, b = blockIdx.y;
    __shared__ float xs[256][33];
    __shared__ float as2[32][36];
    int tid = threadIdx.x;
    float acc[KH] = {};

    for (int l0 = 0; l0 < LL; l0 += 32) {
        int lmax = min(32, LL - l0);
        #pragma unroll
        for (int i = 0; i < 32; i++) {
            int row = (tid >> 5) + i * 8;
            int col = tid & 31;
            float v = 0.f;
            if (l0 + col < LL)
                v = x[((size_t)b * Cc + h * CH + row) * LL + l0 + col];
            xs[row][col] = v;
        }
        #pragma unroll
        for (int i = 0; i < 4; i++) {
            int k   = (tid >> 5) + i * 8;
            int col = tid & 31;
            float v = 0.f;
            if (l0 + col < LL)
                v = attn[(((size_t)b * NH + h) * KH + k) * LL + l0 + col];
            as2[col][k] = v;
        }
        __syncthreads();
        for (int l = 0; l < lmax; l++) {
            float xv = xs[tid][l];
            #pragma unroll
            for (int k4 = 0; k4 < KH / 4; k4++) {
                float4 w = *reinterpret_cast<const float4*>(&as2[l][k4 * 4]);
                acc[k4 * 4 + 0] = fmaf(xv, w.x, acc[k4 * 4 + 0]);
                acc[k4 * 4 + 1] = fmaf(xv, w.y, acc[k4 * 4 + 1]);
                acc[k4 * 4 + 2] = fmaf(xv, w.z, acc[k4 * 4 + 2]);
                acc[k4 * 4 + 3] = fmaf(xv, w.w, acc[k4 * 4 + 3]);
            }
        }
        __syncthreads();
    }
    #pragma unroll
    for (int k = 0; k < KH; k++)
        d_Vt[((size_t)b * KH + k) * Cc + h * CH + tid] = tf32r(acc[k]);
}

// ---------------- final permute: C4[(b,k), j] -> out[(b, j, k)] ----------------
__global__ void permute_kernel(float* __restrict__ out) {
    int idx = blockIdx.x * 256 + threadIdx.x;
    int b = idx >> 13;
    int rem = idx & 8191;
    int j = rem >> 5;
    int k = rem & 31;
    out[OFF_VAL + idx] = d_C4[((size_t)b * KH + k) * OUTC + j];
}

// ---------------- launch ----------------
extern "C" void kernel_launch(void* const* d_in, const int* in_sizes, int n_in,
                              void* d_out, int out_size) {
    const float* x    = (const float*)d_in[0];
    const float* w1_p = (const float*)d_in[1];
    const float* g_p  = (const float*)d_in[2];
    const float* b_p  = (const float*)d_in[3];
    const float* w2_p = (const float*)d_in[4];
    const float* w1_o = (const float*)d_in[5];
    const float* g_o  = (const float*)d_in[6];
    const float* b_o  = (const float*)d_in[7];
    const float* w2_o = (const float*)d_in[8];
    float* out = (float*)d_out;

    float *pX1, *pH1, *pZ, *pVt, *pH2, *pC4;
    float *pW1p, *pW2p, *pW1o, *pW2o;
    cudaGetSymbolAddress((void**)&pX1,  d_X1);
    cudaGetSymbolAddress((void**)&pH1,  d_H1);
    cudaGetSymbolAddress((void**)&pZ,   d_Z);
    cudaGetSymbolAddress((void**)&pVt,  d_Vt);
    cudaGetSymbolAddress((void**)&pH2,  d_H2);
    cudaGetSymbolAddress((void**)&pC4,  d_C4);
    cudaGetSymbolAddress((void**)&pW1p, d_W1p);
    cudaGetSymbolAddress((void**)&pW2p, d_W2p);
    cudaGetSymbolAddress((void**)&pW1o, d_W1o);
    cudaGetSymbolAddress((void**)&pW2o, d_W2o);

    // weight rounding (tf32)
    round_copy<<<(HID * Cc / 4 + 255) / 256, 256>>>(w1_p, pW1p, HID * Cc / 4);
    round_copy<<<(OUTC * HID / 4 + 255) / 256, 256>>>(w2_p, pW2p, OUTC * HID / 4);
    round_copy<<<(HID * Cc / 4 + 255) / 256, 256>>>(w1_o, pW1o, HID * Cc / 4);
    round_copy<<<(OUTC * HID / 4 + 255) / 256, 256>>>(w2_o, pW2o, OUTC * HID / 4);

    // 0) build X1 = concat(pool, x) transposed to (b, l, c), tf32-rounded
    pool_kernel<<<(Bb * Cc) / 8, 256>>>(x);
    transpose_kernel<<<dim3((LL + 31) / 32, Cc / 32, Bb), dim3(32, 8)>>>(x);

    // 1) H1 = X1 @ w1_p^T   (12608 x 2048 x 2048)
    gemm_tf32<4, 2><<<dim3(HID / 128, (N1 + 127) / 128), 256>>>(
        pX1, pW1p, pH1, N1, HID, Cc);

    // 2) BN stats, fold gamma/beta, then BN+ReLU in place
    bn_partial<<<dim3(HID / 32, 64), dim3(32, 8)>>>(pH1, N1, (N1 + 63) / 64);
    bn_final<<<HID / 256, 256>>>(g_p, b_p, 1.f / (float)N1);
    bnrelu_kernel<<<((size_t)N1 * HID / 4 + 255) / 256, 256>>>(pH1, N1 * HID / 4);

    // 3) Z = relu(bn(H1)) @ w2_p^T   (12608 x 256 x 2048)
    gemm_tf32<4, 2><<<dim3(OUTC / 128, (N1 + 127) / 128), 256>>>(
        pH1, pW2p, pZ, N1, OUTC, HID);

    // 4) outputs z_g; norms; softmax -> obj_attn / obj_attn_raw
    zg_kernel<<<(Bb * OUTC) / 256, 256>>>(out);
    norm_kernel<<<Bb * LL, 256>>>();
    softmax_kernel<<<(Bb * OUTC) / 8, 256>>>(out);

    // 5) Vt[(b,k), c] = sum_l x[b,c,l] * attn[b,h,k,l]  (tf32-rounded)
    attnval_kernel<<<dim3(NH, Bb), 256>>>(x, out);

    // 6) H2 = Vt @ w1_o^T   (2048 x 2048 x 2048)
    gemm_tf32<4, 2><<<dim3(HID / 128, N2 / 128), 256>>>(
        pVt, pW1o, pH2, N2, HID, Cc);

    // 7) BN stats 2 + BN/ReLU in place
    bn_partial<<<dim3(HID / 32, 64), dim3(32, 8)>>>(pH2, N2, N2 / 64);
    bn_final<<<HID / 256, 256>>>(g_o, b_o, 1.f / (float)N2);
    bnrelu_kernel<<<((size_t)N2 * HID / 4 + 255) / 256, 256>>>(pH2, N2 * HID / 4);

    // 8) C4 = relu(bn(H2)) @ w2_o^T  (2048 x 256 x 2048) — 64x64 tiles for parallelism
    gemm_tf32<2, 1><<<dim3(OUTC / 64, N2 / 64), 64>>>(
        pH2, pW2o, pC4, N2, OUTC, HID);

    // 9) permute to obj_val layout (b, 256, 32)
    permute_kernel<<<(Bb * OUTC * KH) / 256, 256>>>(out);
}

// round 4
// speedup vs baseline: 5.1008x; 1.7731x over previous
#include <cuda_runtime.h>
#include <cuda_fp16.h>
#include <math.h>
#include <stdint.h>

// ---------------- problem constants ----------------
#define Bb    64
#define Cc    2048
#define LL    196
#define L1    197
#define HID   2048
#define OUTC  256
#define NH    8
#define CH    (Cc / NH)
#define KH    (OUTC / NH)
#define N1    (Bb * L1)     // 12608
#define N2    (Bb * KH)     // 2048
#define KDIM  2048

#define OFF_ZG    0
#define OFF_VAL   (Bb * OUTC)
#define OFF_ATTN  (OFF_VAL + Bb * OUTC * KH)
#define OFF_RAW   (OFF_ATTN + Bb * NH * KH * LL)

// ---------------- device scratch ----------------
__device__ __half d_X1h[(size_t)N1 * Cc];     // (b, l, c) fp16
__device__ float  d_H1[(size_t)N1 * HID];     // GEMM1/3 fp32 out
__device__ __half d_Hh[(size_t)N1 * HID];     // BN+ReLU fp16 (reused for MLP-o)
__device__ float  d_Z [(size_t)N1 * OUTC];
__device__ __half d_Vth[(size_t)N2 * Cc];
__device__ float  d_H2[(size_t)N2 * HID];
__device__ float  d_C4[(size_t)N2 * OUTC];
__device__ float  d_nrm[Bb * LL];
__device__ float  d_part_s[64 * HID];
__device__ float  d_part_q[64 * HID];
__device__ float  d_scale[HID];
__device__ float  d_shift[HID];
__device__ __half d_W1p[(size_t)HID * Cc];
__device__ __half d_W2p[(size_t)OUTC * HID];
__device__ __half d_W1o[(size_t)HID * Cc];
__device__ __half d_W2o[(size_t)OUTC * HID];

// ---------------- helpers ----------------
__device__ __forceinline__ uint32_t smem_u32(const void* p) {
    return (uint32_t)__cvta_generic_to_shared(p);
}

__device__ __forceinline__ void cpasync16_s(uint32_t saddr, const void* g, bool pred) {
    int sz = pred ? 16 : 0;
    asm volatile("cp.async.cg.shared.global [%0], [%1], 16, %2;"
                 :: "r"(saddr), "l"(g), "r"(sz));
}

__device__ __forceinline__ void ldsm4(uint32_t* r, uint32_t addr) {
    asm volatile("ldmatrix.sync.aligned.m8n8.x4.shared.b16 {%0,%1,%2,%3}, [%4];"
                 : "=r"(r[0]), "=r"(r[1]), "=r"(r[2]), "=r"(r[3]) : "r"(addr));
}

__device__ __forceinline__ void mma16816(float* d, const uint32_t* a,
                                         uint32_t b0, uint32_t b1) {
    asm volatile(
        "mma.sync.aligned.m16n8k16.row.col.f32.f16.f16.f32 "
        "{%0,%1,%2,%3}, {%4,%5,%6,%7}, {%8,%9}, {%0,%1,%2,%3};"
        : "+f"(d[0]), "+f"(d[1]), "+f"(d[2]), "+f"(d[3])
        : "r"(a[0]), "r"(a[1]), "r"(a[2]), "r"(a[3]), "r"(b0), "r"(b1));
}

// ================= fp16 mma.sync GEMM =================
// C[R, Cols] = A[R, K=2048] * W[Cols, K]^T.  fp16 in, fp32 accum/out.
// CTA tile 128x256, BK=32 halfs, 8 warps of 64x64, 4-slot cp.async ring.
// SMEM rows padded to 80B (40 halfs) -> conflict-free ldmatrix.
#define GH_A_STG   10240                 // 128 * 80
#define GH_B_STG   20480                 // 256 * 80
#define GH_B_OFF   (4 * GH_A_STG)        // 40960
#define GH_SMEM    (GH_B_OFF + 4 * GH_B_STG)   // 122880
#define GH_NIT     (KDIM / 32)           // 64

__global__ __launch_bounds__(256, 1)
void gemm_h(const __half* __restrict__ A, const __half* __restrict__ W,
            float* __restrict__ C, int R, int Cols)
{
    extern __shared__ char sm[];
    const uint32_t sbase = smem_u32(sm);
    const int tid  = threadIdx.x;
    const int warp = tid >> 5, lane = tid & 31;
    const int wm = warp >> 2, wn = warp & 3;
    const int row0 = blockIdx.y * 128;
    const int col0 = blockIdx.x * 256;

    float acc[4][8][4] = {};

    auto loadStage = [&](int j) {
        const int st = j & 3;
        const uint32_t aB = sbase + st * GH_A_STG;
        const uint32_t bB = sbase + GH_B_OFF + st * GH_B_STG;
        const __half* Aj = A + (size_t)row0 * KDIM + j * 32;
        const __half* Wj = W + (size_t)col0 * KDIM + j * 32;
        #pragma unroll
        for (int i = 0; i < 2; i++) {            // A: 128 rows x 4 chunks
            int task = tid + i * 256;
            int r = task >> 2, ch = task & 3;
            bool p = (row0 + r) < R;
            cpasync16_s(aB + r * 80 + ch * 16,
                        Aj + (size_t)(p ? r : 0) * KDIM + ch * 8, p);
        }
        #pragma unroll
        for (int i = 0; i < 4; i++) {            // B: 256 rows x 4 chunks
            int task = tid + i * 256;
            int r = task >> 2, ch = task & 3;
            cpasync16_s(bB + r * 80 + ch * 16,
                        Wj + (size_t)r * KDIM + ch * 8, true);
        }
        asm volatile("cp.async.commit_group;");
    };

    loadStage(0);
    loadStage(1);

    for (int it = 0; it < GH_NIT; it++) {
        int j = it + 2;
        if (j < GH_NIT) {
            loadStage(j);
            asm volatile("cp.async.wait_group 2;");
        } else {
            asm volatile("cp.async.wait_group 0;");
        }
        __syncthreads();

        const int st = it & 3;
        const uint32_t aB = sbase + st * GH_A_STG;
        const uint32_t bB = sbase + GH_B_OFF + st * GH_B_STG;

        #pragma unroll
        for (int kt = 0; kt < 2; kt++) {
            uint32_t af[4][4], bf[4][4];
            #pragma unroll
            for (int mi = 0; mi < 4; mi++) {
                int rowb = wm * 64 + mi * 16 + (lane & 15);
                uint32_t addr = aB + rowb * 80 + kt * 32 + ((lane >> 4) << 4);
                ldsm4(af[mi], addr);
            }
            #pragma unroll
            for (int jp = 0; jp < 4; jp++) {
                int rown = wn * 64 + jp * 16 + (lane & 7) + ((lane >> 4) << 3);
                uint32_t addr = bB + rown * 80 + kt * 32 + (((lane >> 3) & 1) << 4);
                ldsm4(bf[jp], addr);
            }
            #pragma unroll
            for (int mi = 0; mi < 4; mi++)
                #pragma unroll
                for (int jp = 0; jp < 4; jp++) {
                    mma16816(acc[mi][jp * 2],     af[mi], bf[jp][0], bf[jp][1]);
                    mma16816(acc[mi][jp * 2 + 1], af[mi], bf[jp][2], bf[jp][3]);
                }
        }
    }

    #pragma unroll
    for (int mi = 0; mi < 4; mi++) {
        int rbase = row0 + wm * 64 + mi * 16 + (lane >> 2);
        #pragma unroll
        for (int nj = 0; nj < 8; nj++) {
            int c = col0 + wn * 64 + nj * 8 + (lane & 3) * 2;
            if (rbase < R)
                *reinterpret_cast<float2*>(&C[(size_t)rbase * Cols + c]) =
                    make_float2(acc[mi][nj][0], acc[mi][nj][1]);
            if (rbase + 8 < R)
                *reinterpret_cast<float2*>(&C[(size_t)(rbase + 8) * Cols + c]) =
                    make_float2(acc[mi][nj][2], acc[mi][nj][3]);
        }
    }
}

// ---------------- stage 0: pool ----------------
__global__ void pool_kernel(const float* __restrict__ x) {
    int wid  = (blockIdx.x * blockDim.x + threadIdx.x) >> 5;
    int lane = threadIdx.x & 31;
    if (wid >= Bb * Cc) return;
    int b = wid >> 11, c = wid & (Cc - 1);
    const float* xr = x + ((size_t)b * Cc + c) * LL;
    float s = 0.f;
    for (int l = lane; l < LL; l += 32) s += xr[l];
    #pragma unroll
    for (int o = 16; o; o >>= 1) s += __shfl_down_sync(~0u, s, o);
    if (lane == 0) d_X1h[((size_t)b * L1) * Cc + c] = __float2half_rn(s * (1.f / (float)LL));
}

// ---------------- stage 0b: transpose to (b, 1+l, c) fp16 ----------------
__global__ void transpose_kernel(const float* __restrict__ x) {
    __shared__ float t[32][33];
    int b  = blockIdx.z;
    int c0 = blockIdx.y * 32;
    int l0 = blockIdx.x * 32;
    int tx = threadIdx.x, ty = threadIdx.y;
    #pragma unroll
    for (int i = 0; i < 32; i += 8) {
        int c = c0 + ty + i, l = l0 + tx;
        t[ty + i][tx] = (l < LL) ? x[((size_t)b * Cc + c) * LL + l] : 0.f;
    }
    __syncthreads();
    #pragma unroll
    for (int i = 0; i < 32; i += 8) {
        int l = l0 + ty + i, c = c0 + tx;
        if (l < LL)
            d_X1h[((size_t)b * L1 + 1 + l) * Cc + c] = __float2half_rn(t[tx][ty + i]);
    }
}

// ---------------- fp32 -> fp16 weight copy ----------------
__global__ void half_copy(const float* __restrict__ src, __half* __restrict__ dst, int n4) {
    int i = blockIdx.x * 256 + threadIdx.x;
    if (i >= n4) return;
    float4 v = reinterpret_cast<const float4*>(src)[i];
    __half2 h0 = __floats2half2_rn(v.x, v.y);
    __half2 h1 = __floats2half2_rn(v.z, v.w);
    reinterpret_cast<__half2*>(dst)[i * 2    ] = h0;
    reinterpret_cast<__half2*>(dst)[i * 2 + 1] = h1;
}

// ---------------- BN stats (deterministic two-stage) ----------------
__global__ void bn_partial(const float* __restrict__ Hm, int N, int rpc) {
    int o = blockIdx.x * 32 + threadIdx.x;
    int chunk = blockIdx.y;
    int r0 = chunk * rpc;
    int r1 = min(r0 + rpc, N);
    float s = 0.f, q = 0.f;
    for (int r = r0 + threadIdx.y; r < r1; r += 8) {
        float v = Hm[(size_t)r * HID + o];
        s += v; q += v * v;
    }
    __shared__ float ss[8][32], qq[8][32];
    ss[threadIdx.y][threadIdx.x] = s;
    qq[threadIdx.y][threadIdx.x] = q;
    __syncthreads();
    if (threadIdx.y == 0) {
        #pragma unroll
        for (int i = 1; i < 8; i++) { s += ss[i][threadIdx.x]; q += qq[i][threadIdx.x]; }
        d_part_s[chunk * HID + o] = s;
        d_part_q[chunk * HID + o] = q;
    }
}

__global__ void bn_final(const float* __restrict__ g, const float* __restrict__ bta,
                         float invN) {
    int o = blockIdx.x * 256 + threadIdx.x;
    float s = 0.f, q = 0.f;
    for (int ch = 0; ch < 64; ch++) { s += d_part_s[ch * HID + o]; q += d_part_q[ch * HID + o]; }
    float mu  = s * invN;
    float var = q * invN - mu * mu;
    float sc  = g[o] * rsqrtf(var + 1e-5f);
    d_scale[o] = sc;
    d_shift[o] = bta[o] - mu * sc;
}

// ---------------- BN + ReLU -> fp16 ----------------
__global__ void bnrelu_h(const float* __restrict__ Hm, __half* __restrict__ Ho, int n4) {
    int i = blockIdx.x * 256 + threadIdx.x;
    if (i >= n4) return;
    int c = (i * 4) & (HID - 1);
    float4 v = reinterpret_cast<const float4*>(Hm)[i];
    float a0 = fmaxf(fmaf(v.x, d_scale[c + 0], d_shift[c + 0]), 0.f);
    float a1 = fmaxf(fmaf(v.y, d_scale[c + 1], d_shift[c + 1]), 0.f);
    float a2 = fmaxf(fmaf(v.z, d_scale[c + 2], d_shift[c + 2]), 0.f);
    float a3 = fmaxf(fmaf(v.w, d_scale[c + 3], d_shift[c + 3]), 0.f);
    reinterpret_cast<__half2*>(Ho)[i * 2    ] = __floats2half2_rn(a0, a1);
    reinterpret_cast<__half2*>(Ho)[i * 2 + 1] = __floats2half2_rn(a2, a3);
}

// ---------------- z_g extraction ----------------
__global__ void zg_kernel(float* __restrict__ out) {
    int idx = blockIdx.x * 256 + threadIdx.x;
    int b = idx >> 8, j = idx & 255;
    out[OFF_ZG + idx] = d_Z[((size_t)b * L1) * OUTC + j];
}

// ---------------- feature L2 norm ----------------
__global__ void norm_kernel() {
    int bl = blockIdx.x;
    int b = bl / LL, l = bl % LL;
    float v = d_Z[((size_t)b * L1 + 1 + l) * OUTC + threadIdx.x];
    float s = v * v;
    #pragma unroll
    for (int o = 16; o; o >>= 1) s += __shfl_down_sync(~0u, s, o);
    __shared__ float w[8];
    if ((threadIdx.x & 31) == 0) w[threadIdx.x >> 5] = s;
    __syncthreads();
    if (threadIdx.x == 0) {
        float t = 0.f;
        #pragma unroll
        for (int i = 0; i < 8; i++) t += w[i];
        d_nrm[bl] = sqrtf(t);
    }
}

// ---------------- softmax ----------------
__global__ void softmax_kernel(float* __restrict__ out) {
    int wg   = (blockIdx.x * blockDim.x + threadIdx.x) >> 5;
    int lane = threadIdx.x & 31;
    if (wg >= Bb * OUTC) return;
    int b = wg >> 8, j = wg & 255;
    float v[7];
    float mx = -INFINITY;
    #pragma unroll
    for (int i = 0; i < 7; i++) {
        int l = lane + i * 32;
        if (l < LL) {
            float n = d_nrm[b * LL + l];
            v[i] = d_Z[((size_t)b * L1 + 1 + l) * OUTC + j] / fmaxf(n, 1e-12f);
            mx = fmaxf(mx, v[i]);
        } else v[i] = -INFINITY;
    }
    #pragma unroll
    for (int o = 16; o; o >>= 1) mx = fmaxf(mx, __shfl_xor_sync(~0u, mx, o));
    float s = 0.f;
    #pragma unroll
    for (int i = 0; i < 7; i++) { v[i] = expf(v[i] - mx); s += v[i]; }
    #pragma unroll
    for (int o = 16; o; o >>= 1) s += __shfl_xor_sync(~0u, s, o);
    float inv = 1.f / s;
    #pragma unroll
    for (int i = 0; i < 7; i++) {
        int l = lane + i * 32;
        if (l < LL) {
            float r = v[i] * inv;
            size_t idx = ((size_t)b * OUTC + j) * LL + l;
            out[OFF_ATTN + idx] = r;
            out[OFF_RAW  + idx] = r;
        }
    }
}

// ---------------- attention-value einsum -> fp16 Vt ----------------
__global__ __launch_bounds__(256)
void attnval_kernel(const float* __restrict__ x, const float* __restrict__ out) {
    const float* attn = out + OFF_ATTN;
    int h = blockIdx.x, b = blockIdx.y;
    __shared__ float xs[256][33];
    __shared__ float as2[32][36];
    int tid = threadIdx.x;
    float acc[KH] = {};

    for (int l0 = 0; l0 < LL; l0 += 32) {
        int lmax = min(32, LL - l0);
        #pragma unroll
        for (int i = 0; i < 32; i++) {
            int row = (tid >> 5) + i * 8;
            int col = tid & 31;
            float v = 0.f;
            if (l0 + col < LL)
                v = x[((size_t)b * Cc + h * CH + row) * LL + l0 + col];
            xs[row][col] = v;
        }
        #pragma unroll
        for (int i = 0; i < 4; i++) {
            int k   = (tid >> 5) + i * 8;
            int col = tid & 31;
            float v = 0.f;
            if (l0 + col < LL)
                v = attn[(((size_t)b * NH + h) * KH + k) * LL + l0 + col];
            as2[col][k] = v;
        }
        __syncthreads();
        for (int l = 0; l < lmax; l++) {
            float xv = xs[tid][l];
            #pragma unroll
            for (int k4 = 0; k4 < KH / 4; k4++) {
                float4 w = *reinterpret_cast<const float4*>(&as2[l][k4 * 4]);
                acc[k4 * 4 + 0] = fmaf(xv, w.x, acc[k4 * 4 + 0]);
                acc[k4 * 4 + 1] = fmaf(xv, w.y, acc[k4 * 4 + 1]);
                acc[k4 * 4 + 2] = fmaf(xv, w.z, acc[k4 * 4 + 2]);
                acc[k4 * 4 + 3] = fmaf(xv, w.w, acc[k4 * 4 + 3]);
            }
        }
        __syncthreads();
    }
    #pragma unroll
    for (int k = 0; k < KH; k++)
        d_Vth[((size_t)b * KH + k) * Cc + h * CH + tid] = __float2half_rn(acc[k]);
}

// ---------------- final permute ----------------
__global__ void permute_kernel(float* __restrict__ out) {
    int idx = blockIdx.x * 256 + threadIdx.x;
    int b = idx >> 13;
    int rem = idx & 8191;
    int j = rem >> 5;
    int k = rem & 31;
    out[OFF_VAL + idx] = d_C4[((size_t)b * KH + k) * OUTC + j];
}

// ---------------- launch ----------------
extern "C" void kernel_launch(void* const* d_in, const int* in_sizes, int n_in,
                              void* d_out, int out_size) {
    const float* x    = (const float*)d_in[0];
    const float* w1_p = (const float*)d_in[1];
    const float* g_p  = (const float*)d_in[2];
    const float* b_p  = (const float*)d_in[3];
    const float* w2_p = (const float*)d_in[4];
    const float* w1_o = (const float*)d_in[5];
    const float* g_o  = (const float*)d_in[6];
    const float* b_o  = (const float*)d_in[7];
    const float* w2_o = (const float*)d_in[8];
    float* out = (float*)d_out;

    float *pH1, *pZ, *pH2, *pC4;
    __half *pX1h, *pHh, *pVth, *pW1p, *pW2p, *pW1o, *pW2o;
    cudaGetSymbolAddress((void**)&pX1h, d_X1h);
    cudaGetSymbolAddress((void**)&pH1,  d_H1);
    cudaGetSymbolAddress((void**)&pHh,  d_Hh);
    cudaGetSymbolAddress((void**)&pZ,   d_Z);
    cudaGetSymbolAddress((void**)&pVth, d_Vth);
    cudaGetSymbolAddress((void**)&pH2,  d_H2);
    cudaGetSymbolAddress((void**)&pC4,  d_C4);
    cudaGetSymbolAddress((void**)&pW1p, d_W1p);
    cudaGetSymbolAddress((void**)&pW2p, d_W2p);
    cudaGetSymbolAddress((void**)&pW1o, d_W1o);
    cudaGetSymbolAddress((void**)&pW2o, d_W2o);

    cudaFuncSetAttribute(gemm_h, cudaFuncAttributeMaxDynamicSharedMemorySize, GH_SMEM);

    // weights -> fp16
    half_copy<<<(HID * Cc / 4 + 255) / 256, 256>>>(w1_p, pW1p, HID * Cc / 4);
    half_copy<<<(OUTC * HID / 4 + 255) / 256, 256>>>(w2_p, pW2p, OUTC * HID / 4);
    half_copy<<<(HID * Cc / 4 + 255) / 256, 256>>>(w1_o, pW1o, HID * Cc / 4);
    half_copy<<<(OUTC * HID / 4 + 255) / 256, 256>>>(w2_o, pW2o, OUTC * HID / 4);

    // 0) X1 = concat(pool, x^T) in fp16
    pool_kernel<<<(Bb * Cc) / 8, 256>>>(x);
    transpose_kernel<<<dim3((LL + 31) / 32, Cc / 32, Bb), dim3(32, 8)>>>(x);

    // 1) H1 = X1 @ w1_p^T   (12608 x 2048 x 2048)
    gemm_h<<<dim3(HID / 256, (N1 + 127) / 128), 256, GH_SMEM>>>(pX1h, pW1p, pH1, N1, HID);

    // 2) BN stats + BN/ReLU -> fp16
    bn_partial<<<dim3(HID / 32, 64), dim3(32, 8)>>>(pH1, N1, (N1 + 63) / 64);
    bn_final<<<HID / 256, 256>>>(g_p, b_p, 1.f / (float)N1);
    bnrelu_h<<<((size_t)N1 * HID / 4 + 255) / 256, 256>>>(pH1, pHh, N1 * HID / 4);

    // 3) Z = relu(bn(H1)) @ w2_p^T   (12608 x 256 x 2048)
    gemm_h<<<dim3(OUTC / 256, (N1 + 127) / 128), 256, GH_SMEM>>>(pHh, pW2p, pZ, N1, OUTC);

    // 4) z_g; norms; softmax
    zg_kernel<<<(Bb * OUTC) / 256, 256>>>(out);
    norm_kernel<<<Bb * LL, 256>>>();
    softmax_kernel<<<(Bb * OUTC) / 8, 256>>>(out);

    // 5) attention value -> fp16 Vt
    attnval_kernel<<<dim3(NH, Bb), 256>>>(x, out);

    // 6) H2 = Vt @ w1_o^T   (2048 x 2048 x 2048)
    gemm_h<<<dim3(HID / 256, N2 / 128), 256, GH_SMEM>>>(pVth, pW1o, pH2, N2, HID);

    // 7) BN stats 2 + BN/ReLU -> fp16
    bn_partial<<<dim3(HID / 32, 64), dim3(32, 8)>>>(pH2, N2, N2 / 64);
    bn_final<<<HID / 256, 256>>>(g_o, b_o, 1.f / (float)N2);
    bnrelu_h<<<((size_t)N2 * HID / 4 + 255) / 256, 256>>>(pH2, pHh, N2 * HID / 4);

    // 8) C4 = relu(bn(H2)) @ w2_o^T  (2048 x 256 x 2048)
    gemm_h<<<dim3(OUTC / 256, N2 / 128), 256, GH_SMEM>>>(pHh, pW2o, pC4, N2, OUTC);

    // 9) permute to obj_val layout
    permute_kernel<<<(Bb * OUTC * KH) / 256, 256>>>(out);
}